// round 9
// baseline (speedup 1.0000x reference)
#include <cuda_runtime.h>
#include <math.h>

#define B      8
#define DIM    64
#define HEADS  2
#define CH     32
#define HH     256
#define WW     256
#define NPIX   65536
#define QKVC   192

typedef unsigned long long u64;
__device__ __forceinline__ void fma2(u64& d, u64 a, u64 b, u64 c) {
    asm("fma.rn.f32x2 %0,%1,%2,%3;" : "=l"(d) : "l"(a), "l"(b), "l"(c));
}
__device__ __forceinline__ u64 pk2(float lo, float hi) {
    u64 r; asm("mov.b64 %0,{%1,%2};" : "=l"(r) : "f"(lo), "f"(hi)); return r;
}
__device__ __forceinline__ float2 upk2(u64 v) {
    float2 r; asm("mov.b64 {%0,%1},%2;" : "=f"(r.x), "=f"(r.y) : "l"(v)); return r;
}

__device__ float g_mid[(size_t)B * QKVC * NPIX];
__device__ float g_qkv[(size_t)B * QKVC * NPIX];
__device__ float g_gram[B * HEADS * CH * CH];
__device__ float g_sqn[B * 2 * DIM];
__device__ float g_A[B * HEADS * CH * CH];
__device__ float g_M[B * DIM * DIM];

__global__ void k_zero() {
    int t = blockIdx.x * blockDim.x + threadIdx.x;
    if (t < B * HEADS * CH * CH) g_gram[t] = 0.f;
    if (t < B * 2 * DIM)         g_sqn[t]  = 0.f;
}

// ---- kernel 1: 1x1 conv. grid (512 px-tiles, B, 2 oc-halves) ---------------
// smem: dup'd u64 weights ws2[k][oc]={w,w} (49KB) + xs[ic][128px] (32KB).
// Thread: 6 oc x 4 px-pairs. Inner loop: 3 LDS.128 + 4 LDS.64 + 24 FFMA2.
__global__ __launch_bounds__(256) void k_conv1(const float* __restrict__ x,
                                               const float* __restrict__ wqkv) {
    extern __shared__ float sm[];
    u64*   ws2 = (u64*)sm;            // [64][96] u64
    float* xs  = sm + 64 * 96 * 2;    // [64][128] float

    const int b  = blockIdx.y;
    const int z  = blockIdx.z;
    const long n0 = (long)blockIdx.x * 128;
    const int tx = threadIdx.x, ty = threadIdx.y;
    const int tid = ty * 16 + tx;

    const float* wsrc = wqkv + z * 96 * 64;
    for (int idx = tid; idx < 96 * 64; idx += 256) {
        int oc = idx >> 6, k = idx & 63;
        float w = wsrc[idx];
        ws2[k * 96 + oc] = pk2(w, w);
    }
    const float* xb = x + (size_t)b * DIM * NPIX + n0;
    for (int idx = tid; idx < 64 * 32; idx += 256) {
        int ic = idx >> 5, pv = idx & 31;
        ((float4*)&xs[ic * 128])[pv] = ((const float4*)(xb + (size_t)ic * NPIX))[pv];
    }
    __syncthreads();

    u64 acc[6][4];
#pragma unroll
    for (int p = 0; p < 6; p++)
#pragma unroll
        for (int j = 0; j < 4; j++) acc[p][j] = 0ull;

    const int ocb = ty * 6;
#pragma unroll 4
    for (int k = 0; k < 64; k++) {
        const ulonglong2* wp = (const ulonglong2*)(ws2 + k * 96 + ocb);
        ulonglong2 wA = wp[0], wB = wp[1], wC = wp[2];
        u64 wr[6] = {wA.x, wA.y, wB.x, wB.y, wC.x, wC.y};
        u64 xp[4];
#pragma unroll
        for (int j = 0; j < 4; j++)
            xp[j] = *(const u64*)&xs[k * 128 + 2 * (tx + 16 * j)];
#pragma unroll
        for (int p = 0; p < 6; p++)
#pragma unroll
            for (int j = 0; j < 4; j++)
                fma2(acc[p][j], wr[p], xp[j], acc[p][j]);
    }

    float* ob = g_mid + (size_t)b * QKVC * NPIX + (size_t)(z * 96) * NPIX + n0;
#pragma unroll
    for (int p = 0; p < 6; p++)
#pragma unroll
        for (int j = 0; j < 4; j++) {
            float2 r = upk2(acc[p][j]);
            *(float2*)&ob[(size_t)(ocb + p) * NPIX + 2 * (tx + 16 * j)] = r;
        }
}

// ---- kernel 2: depthwise 3x3 + fused sqn. 32x32 tile, 4 px/thread ----------
__global__ void k_dw(const float* __restrict__ wdw) {
    const int bc = blockIdx.z;
    const int c  = bc % QKVC;
    const int b  = bc / QKVC;
    const int x0 = blockIdx.x * 32, y0 = blockIdx.y * 32;

    __shared__ float tile[34][36];
    const float* in = g_mid + (size_t)bc * NPIX;
    const int tx = threadIdx.x, ty = threadIdx.y;
    const int tid = ty * 8 + tx;

    for (int idx = tid; idx < 34 * 34; idx += 256) {
        int yy = idx / 34, xx = idx % 34;
        int gy = y0 + yy - 1, gx = x0 + xx - 1;
        tile[yy][xx] = (gy >= 0 && gy < HH && gx >= 0 && gx < WW)
                           ? in[gy * WW + gx] : 0.f;
    }
    __syncthreads();

    float w[9];
#pragma unroll
    for (int t = 0; t < 9; t++) w[t] = wdw[c * 9 + t];

    float o0 = 0.f, o1 = 0.f, o2 = 0.f, o3 = 0.f;
#pragma unroll
    for (int ky = 0; ky < 3; ky++) {
        float4 lo = *(float4*)&tile[ty + ky][4 * tx];
        float4 hi = *(float4*)&tile[ty + ky][4 * tx + 4];
        float w0 = w[ky * 3], w1 = w[ky * 3 + 1], w2 = w[ky * 3 + 2];
        o0 = fmaf(w0, lo.x, fmaf(w1, lo.y, fmaf(w2, lo.z, o0)));
        o1 = fmaf(w0, lo.y, fmaf(w1, lo.z, fmaf(w2, lo.w, o1)));
        o2 = fmaf(w0, lo.z, fmaf(w1, lo.w, fmaf(w2, hi.x, o2)));
        o3 = fmaf(w0, lo.w, fmaf(w1, hi.x, fmaf(w2, hi.y, o3)));
    }
    float4 r = make_float4(o0, o1, o2, o3);
    *(float4*)&g_qkv[(size_t)bc * NPIX + (size_t)(y0 + ty) * WW + x0 + 4 * tx] = r;

    if (c < 2 * DIM) {
        float sq = fmaf(o0, o0, fmaf(o1, o1, fmaf(o2, o2, o3 * o3)));
#pragma unroll
        for (int o = 16; o; o >>= 1) sq += __shfl_down_sync(0xffffffffu, sq, o);
        __shared__ float red[8];
        if ((tid & 31) == 0) red[tid >> 5] = sq;
        __syncthreads();
        if (tid == 0) {
            float tot = 0.f;
#pragma unroll
            for (int wv = 0; wv < 8; wv++) tot += red[wv];
            atomicAdd(&g_sqn[b * 2 * DIM + c], tot);
        }
    }
}

// ---- kernel 3: Gram G = q@k^T. 4x4 interleaved f32x2 tile ------------------
__global__ __launch_bounds__(256) void k_gram() {
    __shared__ float qs[32][132];
    __shared__ float ks[32][132];

    const int bh = blockIdx.y;
    const int b = bh >> 1, h = bh & 1;
    const long n0 = (long)blockIdx.x * 1024;
    const float* qg = g_qkv + ((size_t)b * QKVC + h * CH) * NPIX + n0;
    const float* kg = g_qkv + ((size_t)b * QKVC + DIM + h * CH) * NPIX + n0;
    const int tid = threadIdx.x;
    const int g  = tid >> 6;
    const int gi = (tid >> 3) & 7;
    const int gj = tid & 7;

    u64 acc[4][4];
#pragma unroll
    for (int a = 0; a < 4; a++)
#pragma unroll
        for (int bb = 0; bb < 4; bb++) acc[a][bb] = 0ull;

    for (int s = 0; s < 8; s++) {
        __syncthreads();
        for (int idx = tid; idx < 1024; idx += 256) {
            int r = idx >> 5, pv = idx & 31;
            ((float4*)qs[r])[pv] = ((const float4*)(qg + (size_t)r * NPIX + s * 128))[pv];
            ((float4*)ks[r])[pv] = ((const float4*)(kg + (size_t)r * NPIX + s * 128))[pv];
        }
        __syncthreads();
#pragma unroll 4
        for (int p = g * 32; p < g * 32 + 32; p += 4) {
            ulonglong2 qa[4], kb[4];
#pragma unroll
            for (int a = 0; a < 4; a++) qa[a] = *(ulonglong2*)&qs[gi + 8 * a][p];
#pragma unroll
            for (int bb = 0; bb < 4; bb++) kb[bb] = *(ulonglong2*)&ks[gj + 8 * bb][p];
#pragma unroll
            for (int a = 0; a < 4; a++)
#pragma unroll
                for (int bb = 0; bb < 4; bb++) {
                    fma2(acc[a][bb], qa[a].x, kb[bb].x, acc[a][bb]);
                    fma2(acc[a][bb], qa[a].y, kb[bb].y, acc[a][bb]);
                }
        }
    }

    __syncthreads();
    float* red = &qs[0][0];
#pragma unroll
    for (int a = 0; a < 4; a++)
#pragma unroll
        for (int bb = 0; bb < 4; bb++) {
            float2 r = upk2(acc[a][bb]);
            red[g * 1024 + (gi + 8 * a) * 32 + gj + 8 * bb] = r.x + r.y;
        }
    __syncthreads();
    for (int t = tid; t < 1024; t += 256) {
        float s = red[t] + red[1024 + t] + red[2048 + t] + red[3072 + t];
        atomicAdd(&g_gram[bh * 1024 + t], s);
    }
}

// ---- kernel 4: normalize + triple top-k softmax + combine ------------------
__global__ void k_comb(const float* __restrict__ temp, const float* __restrict__ a1,
                       const float* __restrict__ a2, const float* __restrict__ a3) {
    const int bh = blockIdx.x;
    const int b = bh >> 1, h = bh & 1;
    const int i = threadIdx.x;

    __shared__ float nks[CH];
    float nq = fmaxf(sqrtf(g_sqn[b * 2 * DIM + h * CH + i]), 1e-12f);
    float nk = fmaxf(sqrtf(g_sqn[b * 2 * DIM + DIM + h * CH + i]), 1e-12f);
    nks[i] = nk;
    __syncthreads();

    const float t = temp[h];
    float v[CH];
#pragma unroll
    for (int j = 0; j < CH; j++)
        v[j] = g_gram[bh * CH * CH + i * CH + j] / nq * t / nks[j];

    int rank[CH];
#pragma unroll
    for (int j = 0; j < CH; j++) {
        int r = 0; float vj = v[j];
#pragma unroll
        for (int l = 0; l < CH; l++)
            r += (v[l] > vj) || (v[l] == vj && l < j);
        rank[j] = r;
    }
    float mx = -1e30f;
#pragma unroll
    for (int j = 0; j < CH; j++) mx = fmaxf(mx, v[j]);
    float e[CH], s16 = 0.f, s21 = 0.f, s24 = 0.f;
#pragma unroll
    for (int j = 0; j < CH; j++) {
        float ev = expf(v[j] - mx);
        e[j] = ev;
        if (rank[j] < 16) s16 += ev;
        if (rank[j] < 21) s21 += ev;
        if (rank[j] < 24) s24 += ev;
    }
    const float w1 = a1[0] / s16, w2 = a2[0] / s21, w3 = a3[0] / s24;
#pragma unroll
    for (int j = 0; j < CH; j++) {
        float coef = (rank[j] < 16 ? w1 : 0.f) + (rank[j] < 21 ? w2 : 0.f)
                   + (rank[j] < 24 ? w3 : 0.f);
        g_A[bh * CH * CH + i * CH + j] = e[j] * coef;
    }
}

// ---- kernel 5: M[b] = W_proj @ blockdiag(A) --------------------------------
__global__ void k_buildM(const float* __restrict__ wproj) {
    const int b = blockIdx.x;
    __shared__ float As[HEADS * CH * CH];
    __shared__ float Ws[DIM * DIM];
    const int tid = threadIdx.x;
    for (int idx = tid; idx < HEADS * CH * CH; idx += 128) As[idx] = g_A[b * HEADS * CH * CH + idx];
    for (int idx = tid; idx < DIM * DIM; idx += 128)       Ws[idx] = wproj[idx];
    __syncthreads();
#pragma unroll
    for (int m = 0; m < 32; m++) {
        int idx = tid + 128 * m;
        int o = idx >> 6, ci = idx & 63;
        int h = ci >> 5, cj = ci & 31;
        float s = 0.f;
#pragma unroll
        for (int cp = 0; cp < CH; cp++)
            s = fmaf(Ws[o * DIM + h * CH + cp], As[h * CH * CH + cp * CH + cj], s);
        g_M[b * DIM * DIM + idx] = s;
    }
}

// ---- kernel 6: out = M[b] @ v. Dup'd u64 M in smem; 4 oc x 8 px-pairs ------
__global__ __launch_bounds__(256) void k_out(float* __restrict__ out) {
    extern __shared__ float sm[];
    u64*   ms2 = (u64*)sm;            // [64ci][64oc] u64 {m,m}  (32KB)
    float* vs  = sm + 64 * 64 * 2;    // [64][256]               (64KB)
    const int b = blockIdx.y;
    const long n0 = (long)blockIdx.x * 256;
    const int tx = threadIdx.x, ty = threadIdx.y;
    const int tid = ty * 16 + tx;

    const float* Mb = g_M + b * DIM * DIM;
    for (int idx = tid; idx < DIM * DIM; idx += 256) {
        int o = idx >> 6, ci = idx & 63;
        float m = Mb[idx];
        ms2[ci * DIM + o] = pk2(m, m);
    }
    const float* vg = g_qkv + ((size_t)b * QKVC + 2 * DIM) * NPIX + n0;
    for (int idx = tid; idx < 64 * 64; idx += 256) {
        int ci = idx >> 6, pv = idx & 63;
        ((float4*)&vs[ci * 256])[pv] = ((const float4*)(vg + (size_t)ci * NPIX))[pv];
    }
    __syncthreads();

    u64 acc[4][8];
#pragma unroll
    for (int i = 0; i < 4; i++)
#pragma unroll
        for (int j = 0; j < 8; j++) acc[i][j] = 0ull;

    const int ob4 = ty * 4;
#pragma unroll 4
    for (int ci = 0; ci < 64; ci++) {
        const ulonglong2* wp = (const ulonglong2*)(ms2 + ci * DIM + ob4);
        ulonglong2 w01 = wp[0], w23 = wp[1];
        u64 wd[4] = {w01.x, w01.y, w23.x, w23.y};
        u64 xp[8];
#pragma unroll
        for (int j = 0; j < 8; j++)
            xp[j] = *(const u64*)&vs[ci * 256 + 2 * (tx + 16 * j)];
#pragma unroll
        for (int i = 0; i < 4; i++)
#pragma unroll
            for (int j = 0; j < 8; j++)
                fma2(acc[i][j], wd[i], xp[j], acc[i][j]);
    }

    float* ob = out + (size_t)b * DIM * NPIX + n0;
#pragma unroll
    for (int i = 0; i < 4; i++)
#pragma unroll
        for (int j = 0; j < 8; j++) {
            float2 r = upk2(acc[i][j]);
            *(float2*)&ob[(size_t)(ob4 + i) * NPIX + 2 * (tx + 16 * j)] = r;
        }
}

extern "C" void kernel_launch(void* const* d_in, const int* in_sizes, int n_in,
                              void* d_out, int out_size) {
    const float* x     = (const float*)d_in[0];
    const float* wqkv  = (const float*)d_in[1];
    const float* wdw   = (const float*)d_in[2];
    const float* wproj = (const float*)d_in[3];
    const float* temp  = (const float*)d_in[4];
    const float* a1    = (const float*)d_in[5];
    const float* a2    = (const float*)d_in[6];
    const float* a3    = (const float*)d_in[7];
    float* out = (float*)d_out;

    cudaFuncSetAttribute(k_conv1, cudaFuncAttributeMaxDynamicSharedMemorySize, 81920);
    cudaFuncSetAttribute(k_out,   cudaFuncAttributeMaxDynamicSharedMemorySize, 98304);

    k_zero<<<64, 256>>>();
    k_conv1<<<dim3(512, 8, 2), dim3(16, 16), 81920>>>(x, wqkv);
    k_dw<<<dim3(8, 8, B * QKVC), dim3(8, 32)>>>(wdw);
    k_gram<<<dim3(64, 16), 256>>>();
    k_comb<<<16, 32>>>(temp, a1, a2, a3);
    k_buildM<<<8, 128>>>(wproj);
    k_out<<<dim3(256, 8), dim3(16, 16), 98304>>>(out);
}

// round 11
// speedup vs baseline: 1.1070x; 1.1070x over previous
#include <cuda_runtime.h>
#include <math.h>

#define B      8
#define DIM    64
#define HEADS  2
#define CH     32
#define HH     256
#define WW     256
#define NPIX   65536
#define QKVC   192

typedef unsigned long long u64;
__device__ __forceinline__ void fma2(u64& d, u64 a, u64 b, u64 c) {
    asm("fma.rn.f32x2 %0,%1,%2,%3;" : "=l"(d) : "l"(a), "l"(b), "l"(c));
}
__device__ __forceinline__ u64 pk2(float lo, float hi) {
    u64 r; asm("mov.b64 %0,{%1,%2};" : "=l"(r) : "f"(lo), "f"(hi)); return r;
}
__device__ __forceinline__ float2 upk2(u64 v) {
    float2 r; asm("mov.b64 {%0,%1},%2;" : "=f"(r.x), "=f"(r.y) : "l"(v)); return r;
}

__device__ float g_mid[(size_t)B * QKVC * NPIX];
__device__ float g_qkv[(size_t)B * QKVC * NPIX];
__device__ float g_gram[B * HEADS * CH * CH];
__device__ float g_sqn[B * 2 * DIM];
__device__ float g_A[B * HEADS * CH * CH];
__device__ float g_M[B * DIM * DIM];

__global__ void k_zero() {
    int t = blockIdx.x * blockDim.x + threadIdx.x;
    if (t < B * HEADS * CH * CH) g_gram[t] = 0.f;
    if (t < B * 2 * DIM)         g_sqn[t]  = 0.f;
}

// ---- kernel 1: 1x1 conv. grid (512 px-tiles, B, 2 oc-halves) ---------------
// smem 56KB (3 CTA/SM): scalar ws[k][oc] + xs[ic][128].
// Thread: 6 oc x 4 px-pairs. Per k: 6 LDS.32 + 4 LDS.64 + ~6 MOV + 24 FFMA2.
__global__ __launch_bounds__(256) void k_conv1(const float* __restrict__ x,
                                               const float* __restrict__ wqkv) {
    extern __shared__ float sm[];
    float* ws = sm;             // [64][96]
    float* xs = sm + 64 * 96;   // [64][128]

    const int b  = blockIdx.y;
    const int z  = blockIdx.z;
    const long n0 = (long)blockIdx.x * 128;
    const int tx = threadIdx.x, ty = threadIdx.y;
    const int tid = ty * 16 + tx;

    const float* wsrc = wqkv + z * 96 * 64;
    for (int idx = tid; idx < 96 * 64; idx += 256) {
        int oc = idx >> 6, k = idx & 63;
        ws[k * 96 + oc] = wsrc[idx];
    }
    const float* xb = x + (size_t)b * DIM * NPIX + n0;
    for (int idx = tid; idx < 64 * 32; idx += 256) {
        int ic = idx >> 5, pv = idx & 31;
        ((float4*)&xs[ic * 128])[pv] = ((const float4*)(xb + (size_t)ic * NPIX))[pv];
    }
    __syncthreads();

    u64 acc[6][4];
#pragma unroll
    for (int p = 0; p < 6; p++)
#pragma unroll
        for (int j = 0; j < 4; j++) acc[p][j] = 0ull;

    const int ocb = ty * 6;
#pragma unroll 4
    for (int k = 0; k < 64; k++) {
        const float* wrow = ws + k * 96 + ocb;
        u64 wd[6];
#pragma unroll
        for (int p = 0; p < 6; p++) {
            float w = wrow[p];
            wd[p] = pk2(w, w);
        }
        u64 xp[4];
#pragma unroll
        for (int j = 0; j < 4; j++)
            xp[j] = *(const u64*)&xs[k * 128 + 2 * (tx + 16 * j)];
#pragma unroll
        for (int p = 0; p < 6; p++)
#pragma unroll
            for (int j = 0; j < 4; j++)
                fma2(acc[p][j], wd[p], xp[j], acc[p][j]);
    }

    float* ob = g_mid + (size_t)b * QKVC * NPIX + (size_t)(z * 96) * NPIX + n0;
#pragma unroll
    for (int p = 0; p < 6; p++)
#pragma unroll
        for (int j = 0; j < 4; j++) {
            float2 r = upk2(acc[p][j]);
            *(float2*)&ob[(size_t)(ocb + p) * NPIX + 2 * (tx + 16 * j)] = r;
        }
}

// ---- kernel 2: depthwise 3x3 + fused sqn. 64x32 tile, 8 px/thread ----------
// block (8,32): thread (tx,ty) -> row ty, cols {4tx..4tx+3, 32+4tx..32+4tx+3}.
__global__ void k_dw(const float* __restrict__ wdw) {
    const int bc = blockIdx.z;
    const int c  = bc % QKVC;
    const int b  = bc / QKVC;
    const int x0 = blockIdx.x * 64, y0 = blockIdx.y * 32;

    __shared__ float tile[34][68];
    const float* in = g_mid + (size_t)bc * NPIX;
    const int tx = threadIdx.x, ty = threadIdx.y;
    const int tid = ty * 8 + tx;

    for (int idx = tid; idx < 34 * 66; idx += 256) {
        int yy = idx / 66, xx = idx - yy * 66;
        int gy = y0 + yy - 1, gx = x0 + xx - 1;
        tile[yy][xx] = (gy >= 0 && gy < HH && gx >= 0 && gx < WW)
                           ? in[gy * WW + gx] : 0.f;
    }
    __syncthreads();

    float w[9];
#pragma unroll
    for (int t = 0; t < 9; t++) w[t] = wdw[c * 9 + t];

    float sq = 0.f;
#pragma unroll
    for (int half = 0; half < 2; half++) {
        const int bcol = 32 * half + 4 * tx;
        float o0 = 0.f, o1 = 0.f, o2 = 0.f, o3 = 0.f;
#pragma unroll
        for (int ky = 0; ky < 3; ky++) {
            float4 lo = *(float4*)&tile[ty + ky][bcol];
            float4 hi = *(float4*)&tile[ty + ky][bcol + 4];
            float w0 = w[ky * 3], w1 = w[ky * 3 + 1], w2 = w[ky * 3 + 2];
            o0 = fmaf(w0, lo.x, fmaf(w1, lo.y, fmaf(w2, lo.z, o0)));
            o1 = fmaf(w0, lo.y, fmaf(w1, lo.z, fmaf(w2, lo.w, o1)));
            o2 = fmaf(w0, lo.z, fmaf(w1, lo.w, fmaf(w2, hi.x, o2)));
            o3 = fmaf(w0, lo.w, fmaf(w1, hi.x, fmaf(w2, hi.y, o3)));
        }
        *(float4*)&g_qkv[(size_t)bc * NPIX + (size_t)(y0 + ty) * WW + x0 + bcol] =
            make_float4(o0, o1, o2, o3);
        sq = fmaf(o0, o0, fmaf(o1, o1, fmaf(o2, o2, fmaf(o3, o3, sq))));
    }

    if (c < 2 * DIM) {
#pragma unroll
        for (int o = 16; o; o >>= 1) sq += __shfl_down_sync(0xffffffffu, sq, o);
        __shared__ float red[8];
        if ((tid & 31) == 0) red[tid >> 5] = sq;
        __syncthreads();
        if (tid == 0) {
            float tot = 0.f;
#pragma unroll
            for (int wv = 0; wv < 8; wv++) tot += red[wv];
            atomicAdd(&g_sqn[b * 2 * DIM + c], tot);
        }
    }
}

// ---- kernel 3: Gram G = q@k^T. 4x4 interleaved f32x2 tile (unchanged) ------
__global__ __launch_bounds__(256) void k_gram() {
    __shared__ float qs[32][132];
    __shared__ float ks[32][132];

    const int bh = blockIdx.y;
    const int b = bh >> 1, h = bh & 1;
    const long n0 = (long)blockIdx.x * 1024;
    const float* qg = g_qkv + ((size_t)b * QKVC + h * CH) * NPIX + n0;
    const float* kg = g_qkv + ((size_t)b * QKVC + DIM + h * CH) * NPIX + n0;
    const int tid = threadIdx.x;
    const int g  = tid >> 6;
    const int gi = (tid >> 3) & 7;
    const int gj = tid & 7;

    u64 acc[4][4];
#pragma unroll
    for (int a = 0; a < 4; a++)
#pragma unroll
        for (int bb = 0; bb < 4; bb++) acc[a][bb] = 0ull;

    for (int s = 0; s < 8; s++) {
        __syncthreads();
        for (int idx = tid; idx < 1024; idx += 256) {
            int r = idx >> 5, pv = idx & 31;
            ((float4*)qs[r])[pv] = ((const float4*)(qg + (size_t)r * NPIX + s * 128))[pv];
            ((float4*)ks[r])[pv] = ((const float4*)(kg + (size_t)r * NPIX + s * 128))[pv];
        }
        __syncthreads();
#pragma unroll 4
        for (int p = g * 32; p < g * 32 + 32; p += 4) {
            ulonglong2 qa[4], kb[4];
#pragma unroll
            for (int a = 0; a < 4; a++) qa[a] = *(ulonglong2*)&qs[gi + 8 * a][p];
#pragma unroll
            for (int bb = 0; bb < 4; bb++) kb[bb] = *(ulonglong2*)&ks[gj + 8 * bb][p];
#pragma unroll
            for (int a = 0; a < 4; a++)
#pragma unroll
                for (int bb = 0; bb < 4; bb++) {
                    fma2(acc[a][bb], qa[a].x, kb[bb].x, acc[a][bb]);
                    fma2(acc[a][bb], qa[a].y, kb[bb].y, acc[a][bb]);
                }
        }
    }

    __syncthreads();
    float* red = &qs[0][0];
#pragma unroll
    for (int a = 0; a < 4; a++)
#pragma unroll
        for (int bb = 0; bb < 4; bb++) {
            float2 r = upk2(acc[a][bb]);
            red[g * 1024 + (gi + 8 * a) * 32 + gj + 8 * bb] = r.x + r.y;
        }
    __syncthreads();
    for (int t = tid; t < 1024; t += 256) {
        float s = red[t] + red[1024 + t] + red[2048 + t] + red[3072 + t];
        atomicAdd(&g_gram[bh * 1024 + t], s);
    }
}

// ---- kernel 4: normalize + triple top-k softmax + combine ------------------
__global__ void k_comb(const float* __restrict__ temp, const float* __restrict__ a1,
                       const float* __restrict__ a2, const float* __restrict__ a3) {
    const int bh = blockIdx.x;
    const int b = bh >> 1, h = bh & 1;
    const int i = threadIdx.x;

    __shared__ float nks[CH];
    float nq = fmaxf(sqrtf(g_sqn[b * 2 * DIM + h * CH + i]), 1e-12f);
    float nk = fmaxf(sqrtf(g_sqn[b * 2 * DIM + DIM + h * CH + i]), 1e-12f);
    nks[i] = nk;
    __syncthreads();

    const float t = temp[h];
    float v[CH];
#pragma unroll
    for (int j = 0; j < CH; j++)
        v[j] = g_gram[bh * CH * CH + i * CH + j] / nq * t / nks[j];

    int rank[CH];
#pragma unroll
    for (int j = 0; j < CH; j++) {
        int r = 0; float vj = v[j];
#pragma unroll
        for (int l = 0; l < CH; l++)
            r += (v[l] > vj) || (v[l] == vj && l < j);
        rank[j] = r;
    }
    float mx = -1e30f;
#pragma unroll
    for (int j = 0; j < CH; j++) mx = fmaxf(mx, v[j]);
    float e[CH], s16 = 0.f, s21 = 0.f, s24 = 0.f;
#pragma unroll
    for (int j = 0; j < CH; j++) {
        float ev = expf(v[j] - mx);
        e[j] = ev;
        if (rank[j] < 16) s16 += ev;
        if (rank[j] < 21) s21 += ev;
        if (rank[j] < 24) s24 += ev;
    }
    const float w1 = a1[0] / s16, w2 = a2[0] / s21, w3 = a3[0] / s24;
#pragma unroll
    for (int j = 0; j < CH; j++) {
        float coef = (rank[j] < 16 ? w1 : 0.f) + (rank[j] < 21 ? w2 : 0.f)
                   + (rank[j] < 24 ? w3 : 0.f);
        g_A[bh * CH * CH + i * CH + j] = e[j] * coef;
    }
}

// ---- kernel 5: M[b] = W_proj @ blockdiag(A) --------------------------------
__global__ void k_buildM(const float* __restrict__ wproj) {
    const int b = blockIdx.x;
    __shared__ float As[HEADS * CH * CH];
    __shared__ float Ws[DIM * DIM];
    const int tid = threadIdx.x;
    for (int idx = tid; idx < HEADS * CH * CH; idx += 128) As[idx] = g_A[b * HEADS * CH * CH + idx];
    for (int idx = tid; idx < DIM * DIM; idx += 128)       Ws[idx] = wproj[idx];
    __syncthreads();
#pragma unroll
    for (int m = 0; m < 32; m++) {
        int idx = tid + 128 * m;
        int o = idx >> 6, ci = idx & 63;
        int h = ci >> 5, cj = ci & 31;
        float s = 0.f;
#pragma unroll
        for (int cp = 0; cp < CH; cp++)
            s = fmaf(Ws[o * DIM + h * CH + cp], As[h * CH * CH + cp * CH + cj], s);
        g_M[b * DIM * DIM + idx] = s;
    }
}

// ---- kernel 6: out = M[b] @ v. Dup'd u64 M in smem; 4 oc x 8 px-pairs ------
__global__ __launch_bounds__(256) void k_out(float* __restrict__ out) {
    extern __shared__ float sm[];
    u64*   ms2 = (u64*)sm;            // [64ci][64oc] u64 {m,m}
    float* vs  = sm + 64 * 64 * 2;    // [64][256]
    const int b = blockIdx.y;
    const long n0 = (long)blockIdx.x * 256;
    const int tx = threadIdx.x, ty = threadIdx.y;
    const int tid = ty * 16 + tx;

    const float* Mb = g_M + b * DIM * DIM;
    for (int idx = tid; idx < DIM * DIM; idx += 256) {
        int o = idx >> 6, ci = idx & 63;
        float m = Mb[idx];
        ms2[ci * DIM + o] = pk2(m, m);
    }
    const float* vg = g_qkv + ((size_t)b * QKVC + 2 * DIM) * NPIX + n0;
    for (int idx = tid; idx < 64 * 64; idx += 256) {
        int ci = idx >> 6, pv = idx & 63;
        ((float4*)&vs[ci * 256])[pv] = ((const float4*)(vg + (size_t)ci * NPIX))[pv];
    }
    __syncthreads();

    u64 acc[4][8];
#pragma unroll
    for (int i = 0; i < 4; i++)
#pragma unroll
        for (int j = 0; j < 8; j++) acc[i][j] = 0ull;

    const int ob4 = ty * 4;
#pragma unroll 4
    for (int ci = 0; ci < 64; ci++) {
        const ulonglong2* wp = (const ulonglong2*)(ms2 + ci * DIM + ob4);
        ulonglong2 w01 = wp[0], w23 = wp[1];
        u64 wd[4] = {w01.x, w01.y, w23.x, w23.y};
        u64 xp[8];
#pragma unroll
        for (int j = 0; j < 8; j++)
            xp[j] = *(const u64*)&vs[ci * 256 + 2 * (tx + 16 * j)];
#pragma unroll
        for (int i = 0; i < 4; i++)
#pragma unroll
            for (int j = 0; j < 8; j++)
                fma2(acc[i][j], wd[i], xp[j], acc[i][j]);
    }

    float* ob = out + (size_t)b * DIM * NPIX + n0;
#pragma unroll
    for (int i = 0; i < 4; i++)
#pragma unroll
        for (int j = 0; j < 8; j++) {
            float2 r = upk2(acc[i][j]);
            *(float2*)&ob[(size_t)(ob4 + i) * NPIX + 2 * (tx + 16 * j)] = r;
        }
}

extern "C" void kernel_launch(void* const* d_in, const int* in_sizes, int n_in,
                              void* d_out, int out_size) {
    const float* x     = (const float*)d_in[0];
    const float* wqkv  = (const float*)d_in[1];
    const float* wdw   = (const float*)d_in[2];
    const float* wproj = (const float*)d_in[3];
    const float* temp  = (const float*)d_in[4];
    const float* a1    = (const float*)d_in[5];
    const float* a2    = (const float*)d_in[6];
    const float* a3    = (const float*)d_in[7];
    float* out = (float*)d_out;

    cudaFuncSetAttribute(k_conv1, cudaFuncAttributeMaxDynamicSharedMemorySize, 65536);
    cudaFuncSetAttribute(k_out,   cudaFuncAttributeMaxDynamicSharedMemorySize, 98304);

    k_zero<<<64, 256>>>();
    k_conv1<<<dim3(512, 8, 2), dim3(16, 16), 57344>>>(x, wqkv);
    k_dw<<<dim3(4, 8, B * QKVC), dim3(8, 32)>>>(wdw);
    k_gram<<<dim3(64, 16), 256>>>();
    k_comb<<<16, 32>>>(temp, a1, a2, a3);
    k_buildM<<<8, 128>>>(wproj);
    k_out<<<dim3(256, 8), dim3(16, 16), 98304>>>(out);
}